// round 13
// baseline (speedup 1.0000x reference)
#include <cuda_runtime.h>
#include <cuda_bf16.h>

// Problem constants (fixed by reference)
#define BN    4096
#define NTOTN 100000
#define DN    32
#define HN    64
#define TN    8
#define NEGV  (-1e9f)

// Pair-scoped named barrier: 2 warps (64 threads) of one element team.
#define BARP(id) asm volatile("bar.sync %0, 64;" :: "r"(id) : "memory")

// 128 threads = 4 warps = 2 elements; warps (2p, 2p+1) form the team for
// element p. Teams synchronize ONLY via their own named barrier -> elements
// stay fully decoupled (no cross-element lockstep).
// Warp j of a team: loads key rows [16j,16j+16), computes matvec output
// columns [32j,32j+32). Scalar decision chain (LN/argmax/softmax) is
// duplicated in both warps (deterministic => identical result, no sync).
__global__ __launch_bounds__(128, 9)
void gfn_rollout_kernel(const float* __restrict__ qt,         // [B,64]
                        const int*   __restrict__ nbr,        // [NTOT,32]
                        const int*   __restrict__ start,      // [B]
                        const void*  __restrict__ evp,        // [NTOT,32] bool (dtype detected)
                        const float* __restrict__ keys,       // [NTOT,32,64]
                        const float* __restrict__ Wi,         // [64,64]
                        const float* __restrict__ Wh,         // [64,64]
                        const float* __restrict__ Wk,         // [64,64]
                        const float* __restrict__ g,          // [66]
                        const float* __restrict__ be,         // [66]
                        const float* __restrict__ sw,         // [66]
                        const float* __restrict__ sbp,        // [1]
                        const float* __restrict__ temp,       // [1]
                        float* __restrict__ out)
{
    __shared__ __align__(16) float Hsm[2][2][HN];   // [pair][buf][64] hidden (double-buffered)
    __shared__ __align__(16) float Ssel[2][HN];     // selected key row per pair
    __shared__ float Sc[2][DN];                     // scores per pair

    const int tid   = threadIdx.x;
    const int wid   = tid >> 5;
    const int lane  = tid & 31;
    const int p     = wid >> 1;       // pair (element slot) 0..1
    const int j     = wid & 1;        // half index within team
    const int q     = lane & 15;
    const int hh    = lane >> 4;
    const int cq    = q & 7;
    const int b     = blockIdx.x * 2 + p;
    const int barid = p + 1;
    const int c0    = 32 * j + 2 * q;  // matvec column pair owned by this lane

    const float tclamp = fmaxf(temp[0], 1e-5f);
    const float itc    = 1.0f / tclamp;
    const float stop_b = sbp[0];

    // ---- detect edge_valid element width (word-typed int32/float32 vs byte bool) ----
    bool word_typed;
    {
        const unsigned* wv = (const unsigned*)evp;
        bool ok = true;
        #pragma unroll
        for (int i = 0; i < 4; i++) {
            unsigned v = wv[i * 32 + lane];
            ok &= (v == 0u || v == 1u || v == 0x3F800000u);
        }
        word_typed = __all_sync(0xffffffffu, ok);
    }
    const unsigned*      ev32 = (const unsigned*)evp;
    const unsigned char* ev8  = (const unsigned char*)evp;

    // ---- fold LN constants: ((c*rstd)*g+be)*sw == rstd*(Sg - mu*Gsum) + bsum ----
    const float gsw0 = __ldg(&g[lane])      * __ldg(&sw[lane]);
    const float gsw1 = __ldg(&g[lane + 32]) * __ldg(&sw[lane + 32]);
    float gsw64 = 0.f, gsw65 = 0.f;
    float bsum, Gsum;
    {
        float bs = __ldg(&be[lane]) * __ldg(&sw[lane])
                 + __ldg(&be[lane + 32]) * __ldg(&sw[lane + 32]);
        float gs = gsw0 + gsw1;
        if (lane == 0) {
            gsw64 = __ldg(&g[64]) * __ldg(&sw[64]);
            gsw65 = __ldg(&g[65]) * __ldg(&sw[65]);
            bs += __ldg(&be[64]) * __ldg(&sw[64]) + __ldg(&be[65]) * __ldg(&sw[65]);
            gs += gsw64 + gsw65;
        }
        #pragma unroll
        for (int o = 16; o; o >>= 1) {
            bs += __shfl_xor_sync(~0u, bs, o);
            gs += __shfl_xor_sync(~0u, gs, o);
        }
        bsum = bs; Gsum = gs;
    }

    // ---- init hidden = tanh(q[b] @ W_init): duplicated in both warps, j0 writes ----
    {
        float* hb = Hsm[p][0];
        hb[lane]      = qt[b * HN + lane];      // both warps write same values (benign)
        hb[lane + 32] = qt[b * HN + lane + 32];
        BARP(barid);
        float4 acc = make_float4(0.f, 0.f, 0.f, 0.f);
        #pragma unroll
        for (int it = 0; it < 32; it++) {
            int i = 2 * it + hh;
            float hv = hb[i];
            float4 wv = __ldg((const float4*)(Wi + i * HN + 4 * q));
            acc.x += hv * wv.x; acc.y += hv * wv.y;
            acc.z += hv * wv.z; acc.w += hv * wv.w;
        }
        acc.x += __shfl_xor_sync(0xffffffffu, acc.x, 16);
        acc.y += __shfl_xor_sync(0xffffffffu, acc.y, 16);
        acc.z += __shfl_xor_sync(0xffffffffu, acc.z, 16);
        acc.w += __shfl_xor_sync(0xffffffffu, acc.w, 16);
        BARP(barid);   // all reads of staged q done before overwrite
        if (j == 0 && hh == 0) {
            float4 t4 = make_float4(tanhf(acc.x), tanhf(acc.y), tanhf(acc.z), tanhf(acc.w));
            *(float4*)(hb + 4 * q) = t4;
        }
        BARP(barid);
    }

    int   curr     = start[b];
    float lp_total = 0.f;
    int   nmoves   = 0;
    int   buf      = 0;
    int   tstop    = TN;

    // output sections (float32, concatenated reference outputs)
    float* outA   = out;                          // actions_seq  [B,9]
    float* outTot = out + BN * 9;                 // log_pf_total [B]
    float* outS   = out + BN * 9 + BN;            // log_pf_steps [B,9]
    float* outNM  = out + BN * 9 + BN + BN * 9;   // num_moves    [B]

    for (int t = 0; t <= TN; t++) {
        const float*  hb  = Hsm[p][buf];
        const float4* kb4 = (const float4*)(keys + (size_t)curr * (DN * HN));

        // ---- early independent loads (full row each warp, duplicated) ----
        int nb = __ldg(&nbr[(size_t)curr * DN + lane]);
        size_t evi = (size_t)curr * DN + lane;
        int vraw = word_typed ? (ev32[evi] != 0u) : (ev8[evi] != 0);

        // ---- keys gather (rows 16j..16j+15) + partial dots ----
        float4 h4 = ((const float4*)hb)[q];
        float pr[8];
        #pragma unroll
        for (int it = 0; it < 8; it++) {
            float4 v = __ldg(&kb4[(8 * j + it) * 32 + lane]);
            pr[it] = v.x * h4.x + v.y * h4.y + v.z * h4.z + v.w * h4.w;
        }
        // fold chunk q with q^8 (same row, different chunk)
        #pragma unroll
        for (int i = 0; i < 8; i++) pr[i] += __shfl_xor_sync(0xffffffffu, pr[i], 8);
        // transpose-reduce over cq: p[0] ends with row 16j + 2cq + hh
        #pragma unroll
        for (int k = 4; k >= 1; k >>= 1) {
            bool hi = (cq & k) != 0;
            #pragma unroll
            for (int i = 0; i < 4; i++) {
                if (i < k) {
                    float send = hi ? pr[i] : pr[i + k];
                    float recv = __shfl_xor_sync(0xffffffffu, send, k);
                    pr[i] = (hi ? pr[i + k] : pr[i]) + recv;
                }
            }
        }
        if ((lane & 15) < 8) Sc[p][16 * j + 2 * cq + hh] = pr[0];

        // ---- hoisted h @ Wh half-matvec (cols c0,c0+1), overlaps barrier+chain ----
        float acch0 = 0.f, acch1 = 0.f;
        #pragma unroll
        for (int it = 0; it < 32; it++) {
            int i = 2 * it + hh;
            float hv = hb[i];
            float2 w2 = __ldg((const float2*)(Wh + i * HN + c0));
            acch0 += hv * w2.x;
            acch1 += hv * w2.y;
        }

        BARP(barid);   // scores visible

        float sc = Sc[p][lane];
        int vd = (t < TN) ? vraw : 0;
        unsigned vm = __ballot_sync(0xffffffffu, vd);
        float has_edge = vm ? 1.f : 0.f;
        float logit = (vd ? sc : NEGV) * itc;

        // ---- fused single-pass LN (duplicated in both warps) ----
        float x0 = hb[lane], x1 = hb[lane + 32];
        float e64 = (float)t / (float)TN;
        float e65 = has_edge;
        float s1 = x0 + x1;
        float s2 = x0 * x0 + x1 * x1;
        float sg = x0 * gsw0 + x1 * gsw1;
        if (lane == 0) {
            s1 += e64 + e65;
            s2 += e64 * e64 + e65 * e65;
            sg += e64 * gsw64 + e65 * gsw65;
        }
        #pragma unroll
        for (int o = 16; o; o >>= 1) {
            s1 += __shfl_xor_sync(~0u, s1, o);
            s2 += __shfl_xor_sync(~0u, s2, o);
            sg += __shfl_xor_sync(~0u, sg, o);
        }
        float mu = s1 * (1.f / 66.f);
        float var = s2 * (1.f / 66.f) - mu * mu;
        float rstd = rsqrtf(var + 1e-5f);
        float stop_logit = ((sg - mu * Gsum) * rstd + bsum + stop_b) * itc;

        // ---- argmax (first-max by row id = lane), then stop (strict >) ----
        float bv = logit; int bi = lane;
        #pragma unroll
        for (int o = 16; o; o >>= 1) {
            float ov = __shfl_xor_sync(~0u, bv, o);
            int   oi = __shfl_xor_sync(~0u, bi, o);
            if (ov > bv || (ov == bv && oi < bi)) { bv = ov; bi = oi; }
        }
        int action; float chosen;
        if (stop_logit > bv) { action = DN; chosen = stop_logit; }
        else                 { action = bi; chosen = bv; }

        // ---- log-softmax denominator over 33 ----
        float m = fmaxf(bv, stop_logit);
        float es = expf(logit - m);
        #pragma unroll
        for (int o = 16; o; o >>= 1) es += __shfl_xor_sync(~0u, es, o);
        es += expf(stop_logit - m);
        float lp = chosen - (m + logf(es));

        bool chose_stop = (action == DN);
        int  a = chose_stop ? (DN - 1) : action;
        int  act_rec = chose_stop ? -1 : curr * DN + a;

        if (j == 0 && lane == 0) {
            outA[b * 9 + t] = (float)act_rec;
            outS[b * 9 + t] = lp;
        }
        lp_total += lp;
        if (chose_stop) { tstop = t; break; }   // both warps of the team break together
        nmoves++;

        // ---- stage selected key row (warp j: chunks 8j..8j+7) ----
        int tail = __shfl_sync(0xffffffffu, nb, a);
        if (lane < 8) ((float4*)Ssel[p])[8 * j + lane] = __ldg(&kb4[a * 16 + 8 * j + lane]);

        BARP(barid);   // sel row visible

        // ---- finish update: sel @ Wk half, write new hidden to buf^1 ----
        float acc0 = acch0, acc1 = acch1;
        #pragma unroll
        for (int it = 0; it < 32; it++) {
            int i = 2 * it + hh;
            float sv = Ssel[p][i];
            float2 w2 = __ldg((const float2*)(Wk + i * HN + c0));
            acc0 += sv * w2.x;
            acc1 += sv * w2.y;
        }
        acc0 += __shfl_xor_sync(0xffffffffu, acc0, 16);
        acc1 += __shfl_xor_sync(0xffffffffu, acc1, 16);
        if (hh == 0) {
            float2 t2 = make_float2(tanhf(acc0), tanhf(acc1));
            *(float2*)(&Hsm[p][buf ^ 1][c0]) = t2;
        }

        BARP(barid);   // new hidden visible

        buf ^= 1;
        curr = tail;
    }

    // ---- fill forced-stopped tail steps + totals ----
    if (j == 0 && lane == 0) {
        for (int tt = tstop + 1; tt <= TN; tt++) {
            outA[b * 9 + tt] = -1.f;
            outS[b * 9 + tt] = 0.f;
        }
        outTot[b] = lp_total;
        outNM[b]  = (float)nmoves;
    }
}

extern "C" void kernel_launch(void* const* d_in, const int* in_sizes, int n_in,
                              void* d_out, int out_size)
{
    const float* q     = (const float*)d_in[0];
    const int*   nbr   = (const int*)d_in[1];
    const int*   start = (const int*)d_in[2];
    const void*  ev    = (const void*)d_in[3];
    const float* keys  = (const float*)d_in[4];
    const float* Wi    = (const float*)d_in[5];
    const float* Wh    = (const float*)d_in[6];
    const float* Wk    = (const float*)d_in[7];
    const float* g     = (const float*)d_in[8];
    const float* be    = (const float*)d_in[9];
    const float* sw    = (const float*)d_in[10];
    const float* sb    = (const float*)d_in[11];
    const float* temp  = (const float*)d_in[12];
    float* out = (float*)d_out;

    gfn_rollout_kernel<<<BN / 2, 128>>>(q, nbr, start, ev, keys,
                                        Wi, Wh, Wk, g, be, sw, sb, temp, out);
}

// round 14
// speedup vs baseline: 1.6106x; 1.6106x over previous
#include <cuda_runtime.h>
#include <cuda_bf16.h>

// Problem constants (fixed by reference)
#define BN    4096
#define NTOTN 100000
#define DN    32
#define HN    64
#define TN    8
#define NEGV  (-1e9f)

#define PF_L1(p) asm volatile("prefetch.global.L1 [%0];" :: "l"(p))

// One warp per batch element, 4 warps/block, 7 blocks/SM -> whole grid resident
// in a single wave (148*7*4 = 4144 >= 4096 warps). Fully independent warps.
// Lane layout: q = lane&15 (chunk), hh = lane>>4 (row parity); myrow = 2q+hh.
// h@Wh half of the update is hoisted before the decision chain; next node's
// keys/ev/nbr are L1-prefetched as soon as the tail is known (overlapping the
// softmax epilogue + Wk matvec with next-step DRAM latency).
__global__ __launch_bounds__(128, 7)
void gfn_rollout_kernel(const float* __restrict__ qt,         // [B,64]
                        const int*   __restrict__ nbr,        // [NTOT,32]
                        const int*   __restrict__ start,      // [B]
                        const void*  __restrict__ evp,        // [NTOT,32] bool (dtype detected)
                        const float* __restrict__ keys,       // [NTOT,32,64]
                        const float* __restrict__ Wi,         // [64,64]
                        const float* __restrict__ Wh,         // [64,64]
                        const float* __restrict__ Wk,         // [64,64]
                        const float* __restrict__ g,          // [66]
                        const float* __restrict__ be,         // [66]
                        const float* __restrict__ sw,         // [66]
                        const float* __restrict__ sbp,        // [1]
                        const float* __restrict__ temp,       // [1]
                        float* __restrict__ out)
{
    __shared__ float shid[4][HN];   // hidden per warp
    __shared__ float ssel[4][HN];   // selected key row per warp

    const int w     = threadIdx.x >> 5;
    const int lane  = threadIdx.x & 31;
    const int q     = lane & 15;
    const int hh    = lane >> 4;
    const int myrow = 2 * q + hh;
    const int b     = blockIdx.x * 4 + w;

    float* sh = shid[w];
    float* ss = ssel[w];

    const float tclamp = fmaxf(temp[0], 1e-5f);
    const float itc    = 1.0f / tclamp;
    const float stop_b = sbp[0];

    // ---- detect edge_valid element width (word-typed int32/float32 vs byte bool) ----
    bool word_typed;
    {
        const unsigned* wv = (const unsigned*)evp;
        bool ok = true;
        #pragma unroll
        for (int i = 0; i < 4; i++) {
            unsigned v = wv[i * 32 + lane];
            ok &= (v == 0u || v == 1u || v == 0x3F800000u);
        }
        word_typed = __all_sync(0xffffffffu, ok);
    }
    const unsigned*      ev32 = (const unsigned*)evp;
    const unsigned char* ev8  = (const unsigned char*)evp;
    const size_t evsz = word_typed ? 4 : 1;

    // ---- fold LN constants: ((c*rstd)*g+be)*sw == rstd*(Sg - mu*Gsum) + bsum ----
    const float gsw0 = __ldg(&g[lane])      * __ldg(&sw[lane]);
    const float gsw1 = __ldg(&g[lane + 32]) * __ldg(&sw[lane + 32]);
    float gsw64 = 0.f, gsw65 = 0.f;
    float bsum, Gsum;
    {
        float bs = __ldg(&be[lane]) * __ldg(&sw[lane])
                 + __ldg(&be[lane + 32]) * __ldg(&sw[lane + 32]);
        float gs = gsw0 + gsw1;
        if (lane == 0) {
            gsw64 = __ldg(&g[64]) * __ldg(&sw[64]);
            gsw65 = __ldg(&g[65]) * __ldg(&sw[65]);
            bs += __ldg(&be[64]) * __ldg(&sw[64]) + __ldg(&be[65]) * __ldg(&sw[65]);
            gs += gsw64 + gsw65;
        }
        #pragma unroll
        for (int o = 16; o; o >>= 1) {
            bs += __shfl_xor_sync(~0u, bs, o);
            gs += __shfl_xor_sync(~0u, gs, o);
        }
        bsum = bs; Gsum = gs;
    }

    int curr = start[b];

    // ---- prefetch first node's keys/ev/nbr while doing init matvec ----
    {
        const char* nk = (const char*)(keys + (size_t)curr * (DN * HN));
        PF_L1(nk + lane * 256);
        PF_L1(nk + lane * 256 + 128);
        if (lane == 0) {
            PF_L1((const char*)evp + (size_t)curr * DN * evsz);
            PF_L1((const char*)nbr + (size_t)curr * DN * 4);
        }
    }

    // ---- init hidden = tanh(q[b] @ W_init), cooperative row-major matvec ----
    sh[lane]      = qt[b * HN + lane];
    sh[lane + 32] = qt[b * HN + lane + 32];
    __syncwarp();
    {
        float4 acc = make_float4(0.f, 0.f, 0.f, 0.f);
        #pragma unroll
        for (int it = 0; it < 32; it++) {
            int i = 2 * it + hh;
            float hv = sh[i];
            float4 wv = __ldg((const float4*)(Wi + i * HN + 4 * q));
            acc.x += hv * wv.x; acc.y += hv * wv.y;
            acc.z += hv * wv.z; acc.w += hv * wv.w;
        }
        acc.x += __shfl_xor_sync(0xffffffffu, acc.x, 16);
        acc.y += __shfl_xor_sync(0xffffffffu, acc.y, 16);
        acc.z += __shfl_xor_sync(0xffffffffu, acc.z, 16);
        acc.w += __shfl_xor_sync(0xffffffffu, acc.w, 16);
        __syncwarp();
        if (hh == 0) {
            float4 t4 = make_float4(tanhf(acc.x), tanhf(acc.y), tanhf(acc.z), tanhf(acc.w));
            *(float4*)(sh + 4 * q) = t4;
        }
        __syncwarp();
    }

    float lp_total = 0.f;
    int   nmoves   = 0;

    // output sections (float32, concatenated reference outputs)
    float* outA   = out;                          // actions_seq  [B,9]
    float* outTot = out + BN * 9;                 // log_pf_total [B]
    float* outS   = out + BN * 9 + BN;            // log_pf_steps [B,9]
    float* outNM  = out + BN * 9 + BN + BN * 9;   // num_moves    [B]

    int t = 0;
    for (t = 0; t <= TN; t++) {
        const float4* kb4 = (const float4*)(keys + (size_t)curr * (DN * HN));

        // ---- early independent loads: nbr row (tail via shuffle later) + validity ----
        int nb = __ldg(&nbr[(size_t)curr * DN + myrow]);
        size_t evi = (size_t)curr * DN + myrow;
        int vraw = word_typed ? (ev32[evi] != 0u) : (ev8[evi] != 0);

        // ---- fused gather + partial dots: p[it] = <keys[2it+hh], hidden>[chunk q] ----
        float4 h4 = *(const float4*)(sh + 4 * q);
        float p[16];
        #pragma unroll
        for (int it = 0; it < 16; it++) {
            float4 v = __ldg(&kb4[it * 32 + lane]);
            p[it] = v.x * h4.x + v.y * h4.y + v.z * h4.z + v.w * h4.w;
        }

        // ---- transpose-reduce over chunks (within each 16-lane half) ----
        #pragma unroll
        for (int k = 8; k >= 1; k >>= 1) {
            bool hi = (q & k) != 0;
            #pragma unroll
            for (int i = 0; i < 8; i++) {
                if (i < k) {
                    float send = hi ? p[i] : p[i + k];
                    float recv = __shfl_xor_sync(0xffffffffu, send, k);
                    p[i] = (hi ? p[i + k] : p[i]) + recv;
                }
            }
        }
        float sc = p[0];

        // ---- HOISTED h @ Wh half-matvec: independent of LN/argmax chain below ----
        float4 acch = make_float4(0.f, 0.f, 0.f, 0.f);
        #pragma unroll
        for (int it = 0; it < 32; it++) {
            int i = 2 * it + hh;
            float hv = sh[i];
            float4 wh4 = __ldg((const float4*)(Wh + i * HN + 4 * q));
            acch.x += hv * wh4.x; acch.y += hv * wh4.y;
            acch.z += hv * wh4.z; acch.w += hv * wh4.w;
        }

        int vd = (t < TN) ? vraw : 0;
        unsigned vm = __ballot_sync(0xffffffffu, vd);
        float has_edge = vm ? 1.f : 0.f;
        float logit = (vd ? sc : NEGV) * itc;

        // ---- fused single-pass LN (S1, S2, Sg reduced together) ----
        float x0 = sh[lane], x1 = sh[lane + 32];
        float e64 = (float)t / (float)TN;
        float e65 = has_edge;
        float s1 = x0 + x1;
        float s2 = x0 * x0 + x1 * x1;
        float sg = x0 * gsw0 + x1 * gsw1;
        if (lane == 0) {
            s1 += e64 + e65;
            s2 += e64 * e64 + e65 * e65;
            sg += e64 * gsw64 + e65 * gsw65;
        }
        #pragma unroll
        for (int o = 16; o; o >>= 1) {
            s1 += __shfl_xor_sync(~0u, s1, o);
            s2 += __shfl_xor_sync(~0u, s2, o);
            sg += __shfl_xor_sync(~0u, sg, o);
        }
        float mu = s1 * (1.f / 66.f);
        float var = s2 * (1.f / 66.f) - mu * mu;
        float rstd = rsqrtf(var + 1e-5f);
        float stop_logit = ((sg - mu * Gsum) * rstd + bsum + stop_b) * itc;

        // ---- argmax (first-max by row id) over 32 edge logits, then stop (strict >) ----
        float bv = logit; int bi = myrow;
        #pragma unroll
        for (int o = 16; o; o >>= 1) {
            float ov = __shfl_xor_sync(~0u, bv, o);
            int   oi = __shfl_xor_sync(~0u, bi, o);
            if (ov > bv || (ov == bv && oi < bi)) { bv = ov; bi = oi; }
        }
        int action; float chosen;
        if (stop_logit > bv) { action = DN; chosen = stop_logit; }
        else                 { action = bi; chosen = bv; }

        bool chose_stop = (action == DN);
        int  a = chose_stop ? (DN - 1) : action;

        // ---- tail known NOW: prefetch next node's keys/ev/nbr (overlaps epilogue) ----
        int src_lane = (a >> 1) | ((a & 1) << 4);      // lane owning row a
        int tail = __shfl_sync(0xffffffffu, nb, src_lane);
        if (!chose_stop && t < TN) {
            const char* nk = (const char*)(keys + (size_t)tail * (DN * HN));
            PF_L1(nk + lane * 256);
            PF_L1(nk + lane * 256 + 128);
            if (lane == 0) {
                PF_L1((const char*)evp + (size_t)tail * DN * evsz);
                PF_L1((const char*)nbr + (size_t)tail * DN * 4);
            }
        }

        // ---- log-softmax denominator over 33 ----
        float m = fmaxf(bv, stop_logit);
        float es = expf(logit - m);
        #pragma unroll
        for (int o = 16; o; o >>= 1) es += __shfl_xor_sync(~0u, es, o);
        es += expf(stop_logit - m);
        float lp = chosen - (m + logf(es));

        int act_rec = chose_stop ? -1 : curr * DN + a;
        if (lane == 0) {
            outA[b * 9 + t] = (float)act_rec;
            outS[b * 9 + t] = lp;
        }
        lp_total += lp;
        if (chose_stop) break;
        nmoves++;

        // ---- advance: finish with sel @ Wk half ----
        float4 selv = __ldg(&kb4[a * 16 + q]);          // chunk q of chosen row (L1-hot)
        if (hh == 0) *(float4*)(ss + 4 * q) = selv;
        __syncwarp();

        float4 acc = acch;
        #pragma unroll
        for (int it = 0; it < 32; it++) {
            int i = 2 * it + hh;
            float sv = ss[i];
            float4 wk4 = __ldg((const float4*)(Wk + i * HN + 4 * q));
            acc.x += sv * wk4.x; acc.y += sv * wk4.y;
            acc.z += sv * wk4.z; acc.w += sv * wk4.w;
        }
        acc.x += __shfl_xor_sync(0xffffffffu, acc.x, 16);
        acc.y += __shfl_xor_sync(0xffffffffu, acc.y, 16);
        acc.z += __shfl_xor_sync(0xffffffffu, acc.z, 16);
        acc.w += __shfl_xor_sync(0xffffffffu, acc.w, 16);
        __syncwarp();
        if (hh == 0) {
            float4 t4 = make_float4(tanhf(acc.x), tanhf(acc.y), tanhf(acc.z), tanhf(acc.w));
            *(float4*)(sh + 4 * q) = t4;
        }
        __syncwarp();
        curr = tail;
    }

    // ---- fill forced-stopped tail steps + totals ----
    if (lane == 0) {
        for (int tt = t + 1; tt <= TN; tt++) {
            outA[b * 9 + tt] = -1.f;
            outS[b * 9 + tt] = 0.f;
        }
        outTot[b] = lp_total;
        outNM[b]  = (float)nmoves;
    }
}

extern "C" void kernel_launch(void* const* d_in, const int* in_sizes, int n_in,
                              void* d_out, int out_size)
{
    const float* q     = (const float*)d_in[0];
    const int*   nbr   = (const int*)d_in[1];
    const int*   start = (const int*)d_in[2];
    const void*  ev    = (const void*)d_in[3];
    const float* keys  = (const float*)d_in[4];
    const float* Wi    = (const float*)d_in[5];
    const float* Wh    = (const float*)d_in[6];
    const float* Wk    = (const float*)d_in[7];
    const float* g     = (const float*)d_in[8];
    const float* be    = (const float*)d_in[9];
    const float* sw    = (const float*)d_in[10];
    const float* sb    = (const float*)d_in[11];
    const float* temp  = (const float*)d_in[12];
    float* out = (float*)d_out;

    gfn_rollout_kernel<<<BN / 4, 128>>>(q, nbr, start, ev, keys,
                                        Wi, Wh, Wk, g, be, sw, sb, temp, out);
}

// round 15
// speedup vs baseline: 1.9516x; 1.2117x over previous
#include <cuda_runtime.h>
#include <cuda_bf16.h>

// Problem constants (fixed by reference)
#define BN    4096
#define NTOTN 100000
#define DN    32
#define HN    64
#define TN    8
#define NEGV  (-1e9f)

// One warp per batch element, 4 warps/block, 7 blocks/SM -> whole grid resident
// in a single wave. Fully independent warps (no cross-element coupling).
// Lane layout: q = lane&15 (chunk), hh = lane>>4 (row parity); myrow = 2q+hh.
// ev/nbr rows for the NEXT node are loaded as soon as the tail is known
// (carried registers), so the validity mask is ready BEFORE the keys gather,
// enabling a predicated gather that skips invalid rows (~50% of key traffic).
__global__ __launch_bounds__(128, 7)
void gfn_rollout_kernel(const float* __restrict__ qt,         // [B,64]
                        const int*   __restrict__ nbr,        // [NTOT,32]
                        const int*   __restrict__ start,      // [B]
                        const void*  __restrict__ evp,        // [NTOT,32] bool (dtype detected)
                        const float* __restrict__ keys,       // [NTOT,32,64]
                        const float* __restrict__ Wi,         // [64,64]
                        const float* __restrict__ Wh,         // [64,64]
                        const float* __restrict__ Wk,         // [64,64]
                        const float* __restrict__ g,          // [66]
                        const float* __restrict__ be,         // [66]
                        const float* __restrict__ sw,         // [66]
                        const float* __restrict__ sbp,        // [1]
                        const float* __restrict__ temp,       // [1]
                        float* __restrict__ out)
{
    __shared__ float shid[4][HN];   // hidden per warp
    __shared__ float ssel[4][HN];   // selected key row per warp

    const int w     = threadIdx.x >> 5;
    const int lane  = threadIdx.x & 31;
    const int q     = lane & 15;
    const int hh    = lane >> 4;
    const int myrow = 2 * q + hh;
    const int b     = blockIdx.x * 4 + w;

    float* sh = shid[w];
    float* ss = ssel[w];

    const float tclamp = fmaxf(temp[0], 1e-5f);
    const float itc    = 1.0f / tclamp;
    const float stop_b = sbp[0];

    // ---- detect edge_valid element width (word-typed int32/float32 vs byte bool) ----
    bool word_typed;
    {
        const unsigned* wv = (const unsigned*)evp;
        bool ok = true;
        #pragma unroll
        for (int i = 0; i < 4; i++) {
            unsigned v = wv[i * 32 + lane];
            ok &= (v == 0u || v == 1u || v == 0x3F800000u);
        }
        word_typed = __all_sync(0xffffffffu, ok);
    }
    const unsigned*      ev32 = (const unsigned*)evp;
    const unsigned char* ev8  = (const unsigned char*)evp;

    int curr = start[b];

    // ---- carried loads for the first node (row = lane) ----
    int nb   = __ldg(&nbr[(size_t)curr * DN + lane]);
    int vraw = word_typed ? (ev32[(size_t)curr * DN + lane] != 0u)
                          : (ev8 [(size_t)curr * DN + lane] != 0);

    // ---- fold LN constants: ((c*rstd)*g+be)*sw == rstd*(Sg - mu*Gsum) + bsum ----
    const float gsw0 = __ldg(&g[lane])      * __ldg(&sw[lane]);
    const float gsw1 = __ldg(&g[lane + 32]) * __ldg(&sw[lane + 32]);
    float gsw64 = 0.f, gsw65 = 0.f;
    float bsum, Gsum;
    {
        float bs = __ldg(&be[lane]) * __ldg(&sw[lane])
                 + __ldg(&be[lane + 32]) * __ldg(&sw[lane + 32]);
        float gs = gsw0 + gsw1;
        if (lane == 0) {
            gsw64 = __ldg(&g[64]) * __ldg(&sw[64]);
            gsw65 = __ldg(&g[65]) * __ldg(&sw[65]);
            bs += __ldg(&be[64]) * __ldg(&sw[64]) + __ldg(&be[65]) * __ldg(&sw[65]);
            gs += gsw64 + gsw65;
        }
        #pragma unroll
        for (int o = 16; o; o >>= 1) {
            bs += __shfl_xor_sync(~0u, bs, o);
            gs += __shfl_xor_sync(~0u, gs, o);
        }
        bsum = bs; Gsum = gs;
    }

    // ---- init hidden = tanh(q[b] @ W_init), cooperative row-major matvec ----
    sh[lane]      = qt[b * HN + lane];
    sh[lane + 32] = qt[b * HN + lane + 32];
    __syncwarp();
    {
        float4 acc = make_float4(0.f, 0.f, 0.f, 0.f);
        #pragma unroll
        for (int it = 0; it < 32; it++) {
            int i = 2 * it + hh;
            float hv = sh[i];
            float4 wv = __ldg((const float4*)(Wi + i * HN + 4 * q));
            acc.x += hv * wv.x; acc.y += hv * wv.y;
            acc.z += hv * wv.z; acc.w += hv * wv.w;
        }
        acc.x += __shfl_xor_sync(0xffffffffu, acc.x, 16);
        acc.y += __shfl_xor_sync(0xffffffffu, acc.y, 16);
        acc.z += __shfl_xor_sync(0xffffffffu, acc.z, 16);
        acc.w += __shfl_xor_sync(0xffffffffu, acc.w, 16);
        __syncwarp();
        if (hh == 0) {
            float4 t4 = make_float4(tanhf(acc.x), tanhf(acc.y), tanhf(acc.z), tanhf(acc.w));
            *(float4*)(sh + 4 * q) = t4;
        }
        __syncwarp();
    }

    float lp_total = 0.f;
    int   nmoves   = 0;

    // output sections (float32, concatenated reference outputs)
    float* outA   = out;                          // actions_seq  [B,9]
    float* outTot = out + BN * 9;                 // log_pf_total [B]
    float* outS   = out + BN * 9 + BN;            // log_pf_steps [B,9]
    float* outNM  = out + BN * 9 + BN + BN * 9;   // num_moves    [B]

    int t = 0;
    for (t = 0; t <= TN; t++) {
        const float4* kb4 = (const float4*)(keys + (size_t)curr * (DN * HN));

        // ---- row-validity mask (bit r = edge r valid), horizon-masked ----
        unsigned vm = __ballot_sync(0xffffffffu, vraw);
        if (t >= TN) vm = 0u;
        int   vd       = (vm >> myrow) & 1;
        float has_edge = vm ? 1.f : 0.f;

        // ---- PREDICATED gather + partial dots: skip invalid rows entirely ----
        float4 h4 = *(const float4*)(sh + 4 * q);
        float p[16];
        #pragma unroll
        for (int it = 0; it < 16; it++) {
            p[it] = 0.f;
            if ((vm >> (2 * it + hh)) & 1) {
                float4 v = __ldg(&kb4[it * 32 + lane]);
                p[it] = v.x * h4.x + v.y * h4.y + v.z * h4.z + v.w * h4.w;
            }
        }

        // ---- transpose-reduce over chunks (within each 16-lane half) ----
        #pragma unroll
        for (int k = 8; k >= 1; k >>= 1) {
            bool hi = (q & k) != 0;
            #pragma unroll
            for (int i = 0; i < 8; i++) {
                if (i < k) {
                    float send = hi ? p[i] : p[i + k];
                    float recv = __shfl_xor_sync(0xffffffffu, send, k);
                    p[i] = (hi ? p[i + k] : p[i]) + recv;
                }
            }
        }
        float sc = p[0];

        // ---- HOISTED h @ Wh half-matvec: independent of decision chain below ----
        float4 acch = make_float4(0.f, 0.f, 0.f, 0.f);
        #pragma unroll
        for (int it = 0; it < 32; it++) {
            int i = 2 * it + hh;
            float hv = sh[i];
            float4 wh4 = __ldg((const float4*)(Wh + i * HN + 4 * q));
            acch.x += hv * wh4.x; acch.y += hv * wh4.y;
            acch.z += hv * wh4.z; acch.w += hv * wh4.w;
        }

        float logit = (vd ? sc : NEGV) * itc;

        // ---- fused single-pass LN (S1, S2, Sg reduced together) ----
        float x0 = sh[lane], x1 = sh[lane + 32];
        float e64 = (float)t / (float)TN;
        float e65 = has_edge;
        float s1 = x0 + x1;
        float s2 = x0 * x0 + x1 * x1;
        float sg = x0 * gsw0 + x1 * gsw1;
        if (lane == 0) {
            s1 += e64 + e65;
            s2 += e64 * e64 + e65 * e65;
            sg += e64 * gsw64 + e65 * gsw65;
        }
        #pragma unroll
        for (int o = 16; o; o >>= 1) {
            s1 += __shfl_xor_sync(~0u, s1, o);
            s2 += __shfl_xor_sync(~0u, s2, o);
            sg += __shfl_xor_sync(~0u, sg, o);
        }
        float mu = s1 * (1.f / 66.f);
        float var = s2 * (1.f / 66.f) - mu * mu;
        float rstd = rsqrtf(var + 1e-5f);
        float stop_logit = ((sg - mu * Gsum) * rstd + bsum + stop_b) * itc;

        // ---- fused argmax + exp-sum (reference c = stop_logit; exact identity) ----
        float e  = expf(logit - stop_logit);      // 0 for NEG-masked lanes
        float bv = logit; int bi = myrow; float es = e;
        #pragma unroll
        for (int o = 16; o; o >>= 1) {
            float ov  = __shfl_xor_sync(~0u, bv, o);
            int   oi  = __shfl_xor_sync(~0u, bi, o);
            float oes = __shfl_xor_sync(~0u, es, o);
            es += oes;
            if (ov > bv || (ov == bv && oi < bi)) { bv = ov; bi = oi; }
        }
        int action; float chosen;
        if (stop_logit > bv) { action = DN; chosen = stop_logit; }
        else                 { action = bi; chosen = bv; }
        float lp = chosen - (stop_logit + logf(es + 1.0f));

        bool chose_stop = (action == DN);
        int  a = chose_stop ? (DN - 1) : action;
        int  act_rec = chose_stop ? -1 : curr * DN + a;

        if (lane == 0) {
            outA[b * 9 + t] = (float)act_rec;
            outS[b * 9 + t] = lp;
        }
        lp_total += lp;
        if (chose_stop) break;
        nmoves++;

        // ---- tail + carried loads for the NEXT node (hidden under Wk matvec) ----
        int tail = __shfl_sync(0xffffffffu, nb, a);
        int nb_n   = __ldg(&nbr[(size_t)tail * DN + lane]);
        int vraw_n = word_typed ? (ev32[(size_t)tail * DN + lane] != 0u)
                                : (ev8 [(size_t)tail * DN + lane] != 0);

        // ---- advance: finish with sel @ Wk half ----
        float4 selv = __ldg(&kb4[a * 16 + q]);    // chosen row (fetched in gather -> L1)
        if (hh == 0) *(float4*)(ss + 4 * q) = selv;
        __syncwarp();

        float4 acc = acch;
        #pragma unroll
        for (int it = 0; it < 32; it++) {
            int i = 2 * it + hh;
            float sv = ss[i];
            float4 wk4 = __ldg((const float4*)(Wk + i * HN + 4 * q));
            acc.x += sv * wk4.x; acc.y += sv * wk4.y;
            acc.z += sv * wk4.z; acc.w += sv * wk4.w;
        }
        acc.x += __shfl_xor_sync(0xffffffffu, acc.x, 16);
        acc.y += __shfl_xor_sync(0xffffffffu, acc.y, 16);
        acc.z += __shfl_xor_sync(0xffffffffu, acc.z, 16);
        acc.w += __shfl_xor_sync(0xffffffffu, acc.w, 16);
        __syncwarp();
        if (hh == 0) {
            float4 t4 = make_float4(tanhf(acc.x), tanhf(acc.y), tanhf(acc.z), tanhf(acc.w));
            *(float4*)(sh + 4 * q) = t4;
        }
        __syncwarp();

        curr = tail;
        nb   = nb_n;
        vraw = vraw_n;
    }

    // ---- fill forced-stopped tail steps + totals ----
    if (lane == 0) {
        for (int tt = t + 1; tt <= TN; tt++) {
            outA[b * 9 + tt] = -1.f;
            outS[b * 9 + tt] = 0.f;
        }
        outTot[b] = lp_total;
        outNM[b]  = (float)nmoves;
    }
}

extern "C" void kernel_launch(void* const* d_in, const int* in_sizes, int n_in,
                              void* d_out, int out_size)
{
    const float* q     = (const float*)d_in[0];
    const int*   nbr   = (const int*)d_in[1];
    const int*   start = (const int*)d_in[2];
    const void*  ev    = (const void*)d_in[3];
    const float* keys  = (const float*)d_in[4];
    const float* Wi    = (const float*)d_in[5];
    const float* Wh    = (const float*)d_in[6];
    const float* Wk    = (const float*)d_in[7];
    const float* g     = (const float*)d_in[8];
    const float* be    = (const float*)d_in[9];
    const float* sw    = (const float*)d_in[10];
    const float* sb    = (const float*)d_in[11];
    const float* temp  = (const float*)d_in[12];
    float* out = (float*)d_out;

    gfn_rollout_kernel<<<BN / 4, 128>>>(q, nbr, start, ev, keys,
                                        Wi, Wh, Wk, g, be, sw, sb, temp, out);
}